// round 4
// baseline (speedup 1.0000x reference)
#include <cuda_runtime.h>
#include <cuda_bf16.h>
#include <math.h>
#include <stdint.h>

#define NN 100000
#define NE 1000000
#define D  64
#define H  128
#define NL 4
#define NG 64
#define TILE_E 256
#define NT ((NE + TILE_E - 1) / TILE_E)   // 3907
#define EGRID 148
#define ETHREADS 512
#define M1P 260

typedef unsigned long long ull;

// ---------------- persistent device scratch ----------------
__device__ float g_h[NN * D];
__device__ float g_PQ[NN * 256];     // P (cols 0..127) | Q (cols 128..255)
__device__ float g_agg[NN * D];
__device__ float g_rbf[(size_t)NE * 16];
__device__ int   g_kind[NE];
__device__ float g_kt[NL * 2 * H];
__device__ float g_sums[NG * D];
__device__ float g_cnt[NG];

// ---------------- f32x2 helpers ----------------
#define PACK2(d, x, y) asm("mov.b64 %0, {%1,%2};" : "=l"(d) : "r"(__float_as_uint(x)), "r"(__float_as_uint(y)))
#define UNPK2(lo, hi, v) asm("mov.b64 {%0,%1}, %2;" : "=r"(lo), "=r"(hi) : "l"(v))
#define FMA2(acc, a, b) asm("fma.rn.f32x2 %0, %1, %2, %0;" : "+l"(acc) : "l"(a), "l"(b))
#define ADD2(d, a, b)   asm("add.rn.f32x2 %0, %1, %2;" : "=l"(d) : "l"(a), "l"(b))
#define REDV4(p, v0, v1, v2, v3) \
    asm volatile("red.global.add.v4.f32 [%0], {%1,%2,%3,%4};" \
        :: "l"(p), "f"(v0), "f"(v1), "f"(v2), "f"(v3) : "memory")

// ---------------- small kernels ----------------
__global__ void k_init_h(const int* __restrict__ atoms, const float* __restrict__ embed) {
    int i = blockIdx.x * blockDim.x + threadIdx.x;
    if (i < NN * D) g_h[i] = embed[atoms[i >> 6] * D + (i & 63)];
}

__global__ void k_edge_prep(const int* __restrict__ ei, const float* __restrict__ coord,
                            const int* __restrict__ isr) {
    int e = blockIdx.x * blockDim.x + threadIdx.x;
    if (e >= NE) return;
    int s = ei[e], d = ei[NE + e];
    float dx = coord[s * 3 + 0] - coord[d * 3 + 0];
    float dy = coord[s * 3 + 1] - coord[d * 3 + 1];
    float dz = coord[s * 3 + 2] - coord[d * 3 + 2];
    float dist = sqrtf(dx * dx + dy * dy + dz * dz);
    const float coeff = -4.5f;
    float o[16];
#pragma unroll
    for (int g = 0; g < 16; g++) {
        float t = dist - (float)g * (5.0f / 15.0f);
        o[g] = __expf(coeff * t * t);
    }
    float4* dp = (float4*)&g_rbf[(size_t)e * 16];
    dp[0] = make_float4(o[0], o[1], o[2], o[3]);
    dp[1] = make_float4(o[4], o[5], o[6], o[7]);
    dp[2] = make_float4(o[8], o[9], o[10], o[11]);
    dp[3] = make_float4(o[12], o[13], o[14], o[15]);
    g_kind[e] = (isr[s] != isr[d]) ? 1 : 0;
}

__global__ void k_kindtab(const float* __restrict__ subw, const float* __restrict__ W1,
                          const float* __restrict__ b1) {
    int t = blockIdx.x * blockDim.x + threadIdx.x;
    if (t >= NL * 2 * H) return;
    int l = t >> 8, kind = (t >> 7) & 1, j = t & 127;
    const float* W1l = W1 + (size_t)l * 160 * H;
    float v = b1[l * H + j];
#pragma unroll
    for (int g = 0; g < 16; g++)
        v += subw[kind * 16 + g] * W1l[(144 + g) * H + j];
    g_kt[t] = v;
}

__global__ void k_zero_all() {
    int i = blockIdx.x * blockDim.x + threadIdx.x;
    if (i < NN * D) g_agg[i] = 0.f;
    if (i < NG * D) g_sums[i] = 0.f;
    if (i < NG) g_cnt[i] = 0.f;
}

// ---------------- node GEMM fused with relu(h+agg) ----------------
__global__ __launch_bounds__(256) void k_nodegemm(const float* __restrict__ W1, int l) {
    __shared__ float sW[64 * H];     // 32 KB
    __shared__ float sh[64 * 66];    // nodes pitch 66
    const float* W1l = W1 + (size_t)l * 160 * H;
    int tid = threadIdx.x;
    int n0 = blockIdx.x * 64;

    for (int i = tid; i < 4096; i += 256) {
        int e = i >> 6, k = i & 63;
        int n = n0 + e;
        float hv = 0.f;
        if (n < NN) {
            size_t idx = (size_t)n * D + k;
            hv = g_h[idx];
            if (l > 0) {
                hv = fmaxf(hv + g_agg[idx], 0.f);
                g_h[idx] = hv;
                g_agg[idx] = 0.f;
            }
        }
        sh[k * 66 + e] = hv;
    }

    int j = tid & 127;
    int half = tid >> 7;   // nodes half*32 .. +31
    for (int pass = 0; pass < 2; pass++) {
        __syncthreads();
        for (int i = tid; i < 64 * H; i += 256) sW[i] = W1l[pass * 64 * H + i];
        __syncthreads();
        ull acc[16];
#pragma unroll
        for (int q = 0; q < 16; q++) acc[q] = 0ull;
#pragma unroll 4
        for (int k = 0; k < 64; k++) {
            float w = sW[k * H + j];
            ull ww; PACK2(ww, w, w);
            const float* hp = &sh[k * 66 + half * 32];
#pragma unroll
            for (int q = 0; q < 16; q++) {
                ull hv = *(const ull*)&hp[q * 2];
                FMA2(acc[q], hv, ww);
            }
        }
#pragma unroll
        for (int q = 0; q < 16; q++) {
            uint32_t lo, hi; UNPK2(lo, hi, acc[q]);
            int n = n0 + half * 32 + q * 2;
            if (n < NN)     g_PQ[(size_t)n * 256 + pass * 128 + j] = __uint_as_float(lo);
            if (n + 1 < NN) g_PQ[(size_t)(n + 1) * 256 + pass * 128 + j] = __uint_as_float(hi);
        }
    }
}

// ---------------- fused persistent edge kernel ----------------
// smem float offsets
#define SM_M1   0        // 128*260 = 33280
#define SM_W2   33280    // 8192
#define SM_RBF  41472    // 2*4096
#define SM_W1C  49664    // 2048
#define SM_KT   51712    // 256
#define SM_B2   51968    // 64
#define SM_DST  52032    // 512 (2*256)
#define SM_SRC  52544    // 512
#define SM_KND  53056    // 512
#define SMEM_EDGE (53568 * 4)

__global__ __launch_bounds__(ETHREADS, 1) void k_edge(const float* __restrict__ W1,
                                                      const float* __restrict__ W2,
                                                      const float* __restrict__ b2,
                                                      const int* __restrict__ ei, int l) {
    extern __shared__ float sm[];
    float* sM1  = sm + SM_M1;
    float* sW2  = sm + SM_W2;
    float* sRbf = sm + SM_RBF;
    float* sW1C = sm + SM_W1C;
    float* sKt  = sm + SM_KT;
    float* sB2  = sm + SM_B2;
    int*   sDst = (int*)(sm + SM_DST);
    int*   sSrc = (int*)(sm + SM_SRC);
    int*   sKnd = (int*)(sm + SM_KND);

    int tid = threadIdx.x;
    const float* W1l = W1 + (size_t)l * 160 * H;
    const float* W2l = W2 + (size_t)l * H * D;

    for (int i = tid; i < H * D; i += ETHREADS) sW2[i] = W2l[i];
    for (int i = tid; i < 16 * H; i += ETHREADS) sW1C[i] = W1l[128 * H + i];
    if (tid < 256) sKt[tid] = g_kt[l * 256 + tid];
    if (tid < 64) sB2[tid] = b2[l * D + tid];
    __syncthreads();

    const int chunk = (NT + EGRID - 1) / EGRID;   // 27
    int t0 = blockIdx.x * chunk;
    int t1 = t0 + chunk; if (t1 > NT) t1 = NT;
    if (t0 >= t1) return;

    // phase A mapping: 4 cols (jq, jq+32, jq+64, jq+96), 16 edge groups of 16
    const int jq = tid & 31;
    const int egA = tid >> 5;
    // phase B mapping: 8 d x 4 edges
    const int dq = tid & 7;
    const int egB = tid >> 3;
    const int dbase = dq * 8;
    const int ebase = egB * 4;

    // prefetch registers
    int pf_s = 0, pf_k = 0, pf_d = -1;
    float4 pfr0 = make_float4(0, 0, 0, 0), pfr1 = make_float4(0, 0, 0, 0);

    auto prefetch = [&](int tt) {
        if (tt >= NT) return;
        if (tid < 256) {
            int e = tt * TILE_E + tid;
            pf_s = (e < NE) ? ei[e] : 0;
            pf_k = (e < NE) ? g_kind[e] : 0;
        } else {
            int e = tt * TILE_E + tid - 256;
            pf_d = (e < NE) ? ei[NE + e] : -1;
        }
        int i0 = tid * 2;
        const float4* gv = (const float4*)g_rbf;
        int ea = tt * TILE_E + (i0 >> 2);
        pfr0 = (ea < NE) ? gv[(size_t)tt * 1024 + i0] : make_float4(0, 0, 0, 0);
        int eb = tt * TILE_E + ((i0 + 1) >> 2);
        pfr1 = (eb < NE) ? gv[(size_t)tt * 1024 + i0 + 1] : make_float4(0, 0, 0, 0);
    };
    auto store_pf = [&](int tt) {
        if (tt >= NT) return;
        int nb = tt & 1;
        if (tid < 256) { sSrc[nb * 256 + tid] = pf_s; sKnd[nb * 256 + tid] = pf_k; }
        else sDst[nb * 256 + tid - 256] = pf_d;
        float4* rp = (float4*)&sRbf[nb * 4096];
        rp[tid * 2] = pfr0;
        rp[tid * 2 + 1] = pfr1;
    };

    prefetch(t0);
    store_pf(t0);
    __syncthreads();

    for (int t = t0; t < t1; t++) {
        int buf = t & 1;
        prefetch(t + 1);

        // ---- phase A: m1 = silu(P[dst]+Q[src]+kt[kind]+rbf@W1c) ----
        {
            const int* bS = &sSrc[buf * 256];
            const int* bD = &sDst[buf * 256];
            const int* bK = &sKnd[buf * 256];
            const float* bR = &sRbf[buf * 4096];
            // per-tile weight regs (reloaded each tile; barriers block hoisting)
            ull w1a[16], w1b[16];
#pragma unroll
            for (int g = 0; g < 16; g++) {
                PACK2(w1a[g], sW1C[g * H + jq], sW1C[g * H + jq + 32]);
                PACK2(w1b[g], sW1C[g * H + jq + 64], sW1C[g * H + jq + 96]);
            }
            ull kta0, kta1, ktb0, ktb1;
            PACK2(kta0, sKt[jq], sKt[jq + 32]);
            PACK2(kta1, sKt[H + jq], sKt[H + jq + 32]);
            PACK2(ktb0, sKt[jq + 64], sKt[jq + 96]);
            PACK2(ktb1, sKt[H + jq + 64], sKt[H + jq + 96]);

#pragma unroll 2
            for (int ee = 0; ee < 16; ee++) {
                int e = egA * 16 + ee;
                int dn = bD[e], sn = bS[e], kd = bK[e];
                const float* Pp = g_PQ + (size_t)(dn < 0 ? 0 : dn) * 256;
                const float* Qp = g_PQ + (size_t)sn * 256 + 128;
                ull acca, accb;
                PACK2(acca, Pp[jq] + Qp[jq], Pp[jq + 32] + Qp[jq + 32]);
                PACK2(accb, Pp[jq + 64] + Qp[jq + 64], Pp[jq + 96] + Qp[jq + 96]);
                ADD2(acca, acca, kd ? kta1 : kta0);
                ADD2(accb, accb, kd ? ktb1 : ktb0);
                const float* rb = &bR[e * 16];
#pragma unroll
                for (int g = 0; g < 16; g++) {
                    float r = rb[g];
                    ull rr; PACK2(rr, r, r);
                    FMA2(acca, rr, w1a[g]);
                    FMA2(accb, rr, w1b[g]);
                }
                uint32_t u0, u1, u2, u3;
                UNPK2(u0, u1, acca);
                UNPK2(u2, u3, accb);
                float x0 = __uint_as_float(u0), x1 = __uint_as_float(u1);
                float x2 = __uint_as_float(u2), x3 = __uint_as_float(u3);
                sM1[jq * M1P + e]        = __fdividef(x0, 1.f + __expf(-x0));
                sM1[(jq + 32) * M1P + e] = __fdividef(x1, 1.f + __expf(-x1));
                sM1[(jq + 64) * M1P + e] = __fdividef(x2, 1.f + __expf(-x2));
                sM1[(jq + 96) * M1P + e] = __fdividef(x3, 1.f + __expf(-x3));
            }
        }
        store_pf(t + 1);
        __syncthreads();

        // ---- phase B: out = b2 + m1 @ W2; RED.v4 scatter ----
        {
            ull acc[16];
#pragma unroll
            for (int q = 0; q < 16; q++) acc[q] = 0ull;
#pragma unroll 4
            for (int j = 0; j < H; j++) {
                ulonglong2 mm = *(const ulonglong2*)&sM1[j * M1P + ebase];
                float4 w0 = *(const float4*)&sW2[j * D + dbase];
                float4 w1 = *(const float4*)&sW2[j * D + dbase + 4];
                ull ww;
                PACK2(ww, w0.x, w0.x); FMA2(acc[0], mm.x, ww);  FMA2(acc[1], mm.y, ww);
                PACK2(ww, w0.y, w0.y); FMA2(acc[2], mm.x, ww);  FMA2(acc[3], mm.y, ww);
                PACK2(ww, w0.z, w0.z); FMA2(acc[4], mm.x, ww);  FMA2(acc[5], mm.y, ww);
                PACK2(ww, w0.w, w0.w); FMA2(acc[6], mm.x, ww);  FMA2(acc[7], mm.y, ww);
                PACK2(ww, w1.x, w1.x); FMA2(acc[8], mm.x, ww);  FMA2(acc[9], mm.y, ww);
                PACK2(ww, w1.y, w1.y); FMA2(acc[10], mm.x, ww); FMA2(acc[11], mm.y, ww);
                PACK2(ww, w1.z, w1.z); FMA2(acc[12], mm.x, ww); FMA2(acc[13], mm.y, ww);
                PACK2(ww, w1.w, w1.w); FMA2(acc[14], mm.x, ww); FMA2(acc[15], mm.y, ww);
            }
            // add bias (packed: same bias for both edges of a pair)
#pragma unroll
            for (int d = 0; d < 8; d++) {
                float bb = sB2[dbase + d];
                ull bp; PACK2(bp, bb, bb);
                ADD2(acc[2 * d], acc[2 * d], bp);
                ADD2(acc[2 * d + 1], acc[2 * d + 1], bp);
            }
            const int* bD = &sDst[buf * 256];
#pragma unroll
            for (int p = 0; p < 2; p++) {
                float va[8], vb[8];
#pragma unroll
                for (int d = 0; d < 8; d++) {
                    uint32_t lo, hi; UNPK2(lo, hi, acc[2 * d + p]);
                    va[d] = __uint_as_float(lo);
                    vb[d] = __uint_as_float(hi);
                }
                int dn0 = bD[ebase + 2 * p];
                int dn1 = bD[ebase + 2 * p + 1];
                if (dn0 >= 0) {
                    float* ptr = &g_agg[(size_t)dn0 * D + dbase];
                    REDV4(ptr, va[0], va[1], va[2], va[3]);
                    REDV4(ptr + 4, va[4], va[5], va[6], va[7]);
                }
                if (dn1 >= 0) {
                    float* ptr = &g_agg[(size_t)dn1 * D + dbase];
                    REDV4(ptr, vb[0], vb[1], vb[2], vb[3]);
                    REDV4(ptr + 4, vb[4], vb[5], vb[6], vb[7]);
                }
            }
        }
        __syncthreads();
    }
}

// ---------------- pooling (relu fused) ----------------
__global__ void k_pool(const int* __restrict__ batch) {
    int i = blockIdx.x * blockDim.x + threadIdx.x;
    if (i >= NN * D) return;
    int n = i >> 6, d = i & 63;
    float v = fmaxf(g_h[i] + g_agg[i], 0.f);
    atomicAdd(&g_sums[batch[n] * D + d], v);
}

__global__ void k_count(const int* __restrict__ batch) {
    int n = blockIdx.x * blockDim.x + threadIdx.x;
    if (n >= NN) return;
    int b = batch[n];
    unsigned mask = __activemask();
    unsigned m = __match_any_sync(mask, b);
    int leader = __ffs(m) - 1;
    if ((threadIdx.x & 31) == leader) atomicAdd(&g_cnt[b], (float)__popc(m));
}

__global__ void k_final(const float* __restrict__ fcw, const float* __restrict__ fcb,
                        float* __restrict__ out) {
    int g = threadIdx.x;
    if (g < NG) {
        float c = fmaxf(g_cnt[g], 1.f);
        float s = 0.f;
#pragma unroll
        for (int d = 0; d < D; d++) s += g_sums[g * D + d] * fcw[d];
        out[g] = s / c + fcb[0];
    }
}

extern "C" void kernel_launch(void* const* d_in, const int* in_sizes, int n_in,
                              void* d_out, int out_size) {
    const int*   atoms = (const int*)d_in[0];
    const int*   ei    = (const int*)d_in[1];
    const float* coord = (const float*)d_in[2];
    const int*   isr   = (const int*)d_in[3];
    const int*   batch = (const int*)d_in[4];
    const float* embed = (const float*)d_in[5];
    const float* subw  = (const float*)d_in[6];
    const float* W1    = (const float*)d_in[7];
    const float* b1    = (const float*)d_in[8];
    const float* W2    = (const float*)d_in[9];
    const float* b2    = (const float*)d_in[10];
    const float* fcw   = (const float*)d_in[11];
    const float* fcb   = (const float*)d_in[12];
    float* out = (float*)d_out;

    cudaFuncSetAttribute(k_edge, cudaFuncAttributeMaxDynamicSharedMemorySize, SMEM_EDGE);

    const int T = 256;
    k_init_h<<<(NN * D + T - 1) / T, T>>>(atoms, embed);
    k_edge_prep<<<(NE + T - 1) / T, T>>>(ei, coord, isr);
    k_kindtab<<<4, 256>>>(subw, W1, b1);
    k_zero_all<<<(NN * D + T - 1) / T, T>>>();

    for (int l = 0; l < NL; l++) {
        k_nodegemm<<<(NN + 63) / 64, 256>>>(W1, l);
        k_edge<<<EGRID, ETHREADS, SMEM_EDGE>>>(W1, W2, b2, ei, l);
    }

    k_pool<<<(NN * D + T - 1) / T, T>>>(batch);
    k_count<<<(NN + T - 1) / T, T>>>(batch);
    k_final<<<1, 64>>>(fcw, fcb, out);
}